// round 15
// baseline (speedup 1.0000x reference)
#include <cuda_runtime.h>
#include <cstdint>

// Space-to-depth k=2: in [32, 224, 224, 64] f32 -> out [32, 112, 112, 256]
// out[b, ho, wo, kh*128 + kw*64 + c] = in[b, 2*ho+kh, 2*wo+kw, c]
//
// Chunk view (float4 units, C4=16 float4s/pixel):
//   input row-pair (b, 2ho..2ho+1) and output row (b, ho) are both 7168
//   contiguous float4s starting at the SAME offset chunk*7168 (chunk=b*112+ho).
// Within a chunk, output-local offset o (0..7167) maps to input-local:
//   in_off = ((o>>5)&1)*3584 + (o>>6)*32 + (o&31)
// Warp of 32 consecutive o -> one contiguous 512B load + one 512B store
// (fully coalesced both directions).
//
// R15: store-policy A/B on the best config (512thr x 7 items, MLP=7,
// __ldcs loads). Stores switched __stcs -> __stwt (st.global.wt):
// write-through, no L2 allocation for the 411MB zero-reuse output stream.
// Hypothesis: removing store lines from L2 frees LTS slots/tags for the
// read stream and simplifies the DRAM interleave. Counter-risk: losing
// L2's write-combining depth serializes stores at the controller.
// R13 already showed policy choices are worth measurable µs here.

static constexpr int      THREADS  = 512;
static constexpr int      ITEMS    = 7;
static constexpr unsigned TILE_F4  = THREADS * ITEMS;    // 3584 = half chunk
static constexpr unsigned CHUNK_F4 = 7168;               // 2*224*16 = 112*64
static constexpr unsigned GRID     = 32u * 112u * 2u;    // 7168 tiles

__global__ void __launch_bounds__(THREADS)
s2d_kernel(const float4* __restrict__ in, float4* __restrict__ out)
{
    const unsigned chunk = blockIdx.x >> 1;              // 0..3583
    const unsigned half  = blockIdx.x & 1u;              // 0..1
    const unsigned base  = chunk * CHUNK_F4;
    const unsigned o0    = half * TILE_F4 + threadIdx.x; // 0..7167

    // bits 0..8 of o are invariant across items (stride 512), so the
    // in/out offsets advance by constant 256 / 512 float4s per item.
    const unsigned in0  = base + ((o0 >> 5) & 1u) * 3584u
                               + (o0 >> 6) * 32u
                               + (o0 & 31u);
    const unsigned out0 = base + o0;

    float4 v[ITEMS];
#pragma unroll
    for (int j = 0; j < ITEMS; j++)
        v[j] = __ldcs(in + in0 + (unsigned)j * 256u);
#pragma unroll
    for (int j = 0; j < ITEMS; j++)
        __stwt(out + out0 + (unsigned)j * 512u, v[j]);
}

extern "C" void kernel_launch(void* const* d_in, const int* in_sizes, int n_in,
                              void* d_out, int out_size)
{
    (void)in_sizes; (void)n_in; (void)out_size;
    const float4* in  = (const float4*)d_in[0];
    float4*       out = (float4*)d_out;

    s2d_kernel<<<GRID, THREADS>>>(in, out);
}

// round 16
// speedup vs baseline: 1.0161x; 1.0161x over previous
#include <cuda_runtime.h>
#include <cstdint>

// Space-to-depth k=2: in [32, 224, 224, 64] f32 -> out [32, 112, 112, 256]
// out[b, ho, wo, kh*128 + kw*64 + c] = in[b, 2*ho+kh, 2*wo+kw, c]
//
// Chunk view (float4 units, C4=16 float4s/pixel):
//   input row-pair (b, 2ho..2ho+1) and output row (b, ho) are both 7168
//   contiguous float4s starting at the SAME offset chunk*7168 (chunk=b*112+ho).
// Within a chunk, output-local offset o (0..7167) maps to input-local:
//   in_off = ((o>>5)&1)*3584 + (o>>6)*32 + (o&31)
// Warp of 32 consecutive o -> one contiguous 512B load + one 512B store
// (fully coalesced both directions).
//
// FINAL (best measured config; R10/R12/R14 cluster 113.9/115.2/114.5us):
// THREADS=512, ITEMS=7 -> tile = 3584 float4s = half a chunk, 2 blocks per
// chunk, grid = 7168. Item stride 512 is a multiple of 64 -> c4 bits
// invariant: in_off advances by exactly 256, out by 512 per item (pure-add
// loop body). All 7 LDG.128 issued before any STG (MLP=7). Streaming hints
// __ldcs/__stcs: isolated A/B (R13) showed default policy costs ~3.5us
// (L1 40->64%, DRAM 84->82); __stwt (R15) measured neutral vs __stcs.
//
// Convergence: 13 measurements spanning occ 31-84%, MLP 1-8, grid shapes
// 1184-100352 + persistent, 3 cache policies — all tuned configs pin at
// 84.5+-0.7% DRAM / ~6.7 TB/s combined = the path-independent LTS/HBM
// ceiling. Traffic is irreducible (pure permutation, zero reuse, every
// byte moves exactly once). ~114us kernel / ~121.2us bench is the floor.

static constexpr int      THREADS  = 512;
static constexpr int      ITEMS    = 7;
static constexpr unsigned TILE_F4  = THREADS * ITEMS;    // 3584 = half chunk
static constexpr unsigned CHUNK_F4 = 7168;               // 2*224*16 = 112*64
static constexpr unsigned GRID     = 32u * 112u * 2u;    // 7168 tiles

__global__ void __launch_bounds__(THREADS)
s2d_kernel(const float4* __restrict__ in, float4* __restrict__ out)
{
    const unsigned chunk = blockIdx.x >> 1;              // 0..3583
    const unsigned half  = blockIdx.x & 1u;              // 0..1
    const unsigned base  = chunk * CHUNK_F4;
    const unsigned o0    = half * TILE_F4 + threadIdx.x; // 0..7167

    // bits 0..8 of o are invariant across items (stride 512), so the
    // in/out offsets advance by constant 256 / 512 float4s per item.
    const unsigned in0  = base + ((o0 >> 5) & 1u) * 3584u
                               + (o0 >> 6) * 32u
                               + (o0 & 31u);
    const unsigned out0 = base + o0;

    float4 v[ITEMS];
#pragma unroll
    for (int j = 0; j < ITEMS; j++)
        v[j] = __ldcs(in + in0 + (unsigned)j * 256u);
#pragma unroll
    for (int j = 0; j < ITEMS; j++)
        __stcs(out + out0 + (unsigned)j * 512u, v[j]);
}

extern "C" void kernel_launch(void* const* d_in, const int* in_sizes, int n_in,
                              void* d_out, int out_size)
{
    (void)in_sizes; (void)n_in; (void)out_size;
    const float4* in  = (const float4*)d_in[0];
    float4*       out = (float4*)d_out;

    s2d_kernel<<<GRID, THREADS>>>(in, out);
}